// round 2
// baseline (speedup 1.0000x reference)
#include <cuda_runtime.h>

#define N     2048
#define FIN   512
#define F     64
#define NEG_BIG -9.0e15f

typedef unsigned long long u64;

// ---------------- scratch (static device allocations only) ----------------
__device__ float g_h[N * F];                 // 512 KB
__device__ float g_S[(size_t)N * N];         // 16 MB raw scores
__device__ float g_rowmax[N];
__device__ float g_rowsum[N];
__device__ float g_opart[4][N * F];          // 2 MB: j-split partials of P@h

#define ABS2MASK 0x7FFFFFFF7FFFFFFFULL

__device__ __forceinline__ u64 f2add(u64 a, u64 b) {
    u64 r; asm("add.rn.f32x2 %0, %1, %2;" : "=l"(r) : "l"(a), "l"(b)); return r;
}
__device__ __forceinline__ u64 f2fma(u64 a, u64 b, u64 c) {
    u64 r; asm("fma.rn.f32x2 %0, %1, %2, %3;" : "=l"(r) : "l"(a), "l"(b), "l"(c)); return r;
}
__device__ __forceinline__ u64 dupf(float x) {
    u64 r; unsigned u = __float_as_uint(x);
    asm("mov.b64 %0, {%1,%1};" : "=l"(r) : "r"(u)); return r;
}
__device__ __forceinline__ float unpack_sum(u64 v) {
    float lo, hi;
    asm("mov.b64 {%0,%1}, %2;" : "=f"(lo), "=f"(hi) : "l"(v));
    return lo + hi;
}
__device__ __forceinline__ void unpack2(u64 v, float& lo, float& hi) {
    asm("mov.b64 {%0,%1}, %2;" : "=f"(lo), "=f"(hi) : "l"(v));
}

#define FMA4(a, s, v) { (a).x += (s)*(v).x; (a).y += (s)*(v).y; (a).z += (s)*(v).z; (a).w += (s)*(v).w; }

// ---------------- init ------------------------------------------------------
__global__ void init_rows() {
    int i = blockIdx.x * blockDim.x + threadIdx.x;
    if (i < N) { g_rowmax[i] = 0.0f; g_rowsum[i] = 0.0f; }
}

// ---------------- K1: h = x @ W  (N x FIN) @ (FIN x F) ---------------------
__global__ __launch_bounds__(256) void k1_gemm_h(const float* __restrict__ x,
                                                 const float* __restrict__ W) {
    __shared__ float xs[16][FIN];   // 32 KB
    __shared__ float ws[32][F];     // 8 KB
    int tid = threadIdx.x;
    int r0 = blockIdx.x * 16;

    const float4* xg  = (const float4*)(x + (size_t)r0 * FIN);
    float4*       xs4 = (float4*)&xs[0][0];
#pragma unroll
    for (int u = 0; u < 8; u++) xs4[tid + u * 256] = xg[tid + u * 256];

    int tx = tid & 15;
    int ty = tid >> 4;
    float4 acc = {0.f, 0.f, 0.f, 0.f};

    for (int kt = 0; kt < FIN; kt += 32) {
        __syncthreads();
        const float4* wg  = (const float4*)(W + (size_t)kt * F);
        float4*       ws4 = (float4*)&ws[0][0];
        ws4[tid]       = wg[tid];
        ws4[tid + 256] = wg[tid + 256];
        __syncthreads();
#pragma unroll
        for (int k4 = 0; k4 < 8; k4++) {
            float4 xv = *(const float4*)&xs[ty][kt + k4 * 4];
            float4 w0 = ((const float4*)&ws[k4 * 4 + 0][0])[tx];
            float4 w1 = ((const float4*)&ws[k4 * 4 + 1][0])[tx];
            float4 w2 = ((const float4*)&ws[k4 * 4 + 2][0])[tx];
            float4 w3 = ((const float4*)&ws[k4 * 4 + 3][0])[tx];
            FMA4(acc, xv.x, w0); FMA4(acc, xv.y, w1);
            FMA4(acc, xv.z, w2); FMA4(acc, xv.w, w3);
        }
    }
    *(float4*)&g_h[(size_t)(r0 + ty) * F + tx * 4] = acc;
}

// ---------------- K2: scores S[i,j] = adj ? relu(sum_f |h_i-h_j|*a_f) : NEG_BIG
// 64x64 tile, 4i x 4j register micro-tiles, packed f32x2 over f.
// h_j stored NEGATED so diff = add.f32x2; abs via 64-bit AND (alu pipe).
__global__ __launch_bounds__(256) void k2_scores(const int* __restrict__ adj,
                                                 const float* __restrict__ a) {
    __shared__ float his[64][F];    // 16 KB  [i][f]
    __shared__ float nhjs[64][F];   // 16 KB  [j][f]  (negated)
    __shared__ float as_[F];

    int tid = threadIdx.x;
    int jb = blockIdx.x, ib = blockIdx.y;

    const float4* hgi = (const float4*)(g_h + (size_t)ib * 64 * F);
    const float4* hgj = (const float4*)(g_h + (size_t)jb * 64 * F);
    float4* hip = (float4*)&his[0][0];
    float4* hjp = (float4*)&nhjs[0][0];
#pragma unroll
    for (int u = 0; u < 4; u++) {
        hip[tid + u * 256] = hgi[tid + u * 256];
        float4 v = hgj[tid + u * 256];
        v.x = -v.x; v.y = -v.y; v.z = -v.z; v.w = -v.w;
        hjp[tid + u * 256] = v;
    }
    if (tid < 16) ((float4*)as_)[tid] = ((const float4*)a)[tid];
    __syncthreads();

    int tx = tid & 15, ty = tid >> 4;
    int i0 = ty * 4, j0 = tx * 4;
    u64 acc[4][4] = {};

#pragma unroll
    for (int fc = 0; fc < 16; fc++) {
        int c2 = (fc + tx) & 15;               // rotated f-chunk vs banks
        ulonglong2 av = *(const ulonglong2*)&as_[c2 * 4];
        ulonglong2 hi[4], nj[4];
#pragma unroll
        for (int k = 0; k < 4; k++) {
            hi[k] = *(const ulonglong2*)&his [i0 + k][c2 * 4];
            nj[k] = *(const ulonglong2*)&nhjs[j0 + k][c2 * 4];
        }
#pragma unroll
        for (int k = 0; k < 4; k++) {
#pragma unroll
            for (int jj = 0; jj < 4; jj++) {
                u64 d0 = f2add(hi[k].x, nj[jj].x) & ABS2MASK;
                acc[k][jj] = f2fma(d0, av.x, acc[k][jj]);
                u64 d1 = f2add(hi[k].y, nj[jj].y) & ABS2MASK;
                acc[k][jj] = f2fma(d1, av.y, acc[k][jj]);
            }
        }
    }

    int gi0 = ib * 64 + i0, gj0 = jb * 64 + j0;
#pragma unroll
    for (int k = 0; k < 4; k++) {
        int4 ad = *(const int4*)&adj[(size_t)(gi0 + k) * N + gj0];
        float4 s;
        s.x = (ad.x > 0) ? fmaxf(unpack_sum(acc[k][0]), 0.f) : NEG_BIG;
        s.y = (ad.y > 0) ? fmaxf(unpack_sum(acc[k][1]), 0.f) : NEG_BIG;
        s.z = (ad.z > 0) ? fmaxf(unpack_sum(acc[k][2]), 0.f) : NEG_BIG;
        s.w = (ad.w > 0) ? fmaxf(unpack_sum(acc[k][3]), 0.f) : NEG_BIG;
        float m = fmaxf(fmaxf(s.x, s.y), fmaxf(s.z, s.w));
#pragma unroll
        for (int o = 8; o >= 1; o >>= 1)
            m = fmaxf(m, __shfl_xor_sync(0xffffffffu, m, o));
        if (tx == 0 && m >= 0.f)
            atomicMax((int*)&g_rowmax[gi0 + k], __float_as_int(m)); // valid: values >= 0
        *(float4*)&g_S[(size_t)(gi0 + k) * N + gj0] = s;
    }
}

// ---------------- K3: fused exp + rowsum + P@h -----------------------------
// Block: 32 i-rows x full F; j split into 4 chunks of 512 (gy), 8 tiles of 64.
// Staging applies p = exp(s - rowmax) once per element, accumulating rowsum.
// Micro: thread = 1 row x 8 features (4 packed), packed f32x2 FMAs.
__global__ __launch_bounds__(256) void k3_av() {
    __shared__ float Ps[32][72];    // padded: stride 72 (16B-aligned, banks spread)
    __shared__ float hs[64][F];     // 16 KB
    __shared__ float ms[32];
    int tid = threadIdx.x;
    int ib = blockIdx.x;            // 64 blocks of 32 rows
    int gy = blockIdx.y;            // 4 j-splits
    int row0 = ib * 32;
    if (tid < 32) ms[tid] = g_rowmax[row0 + tid];

    int tx = tid & 7, ty = tid >> 3;     // micro: row ty, features tx*8..+8
    int sr = tid >> 4, sc = tid & 15;    // staging: rows sr, sr+16; f4-col sc
    u64 acc0 = 0, acc1 = 0, acc2 = 0, acc3 = 0;
    float rsum0 = 0.f, rsum1 = 0.f;
    __syncthreads();
    float m0 = ms[sr], m1 = ms[sr + 16];

    for (int jt = 0; jt < 8; jt++) {
        int j0 = gy * 512 + jt * 64;
        __syncthreads();
        // stage Ps with fused exp + rowsum
        {
            float4 s0 = *(const float4*)&g_S[(size_t)(row0 + sr)      * N + j0 + sc * 4];
            float4 s1 = *(const float4*)&g_S[(size_t)(row0 + sr + 16) * N + j0 + sc * 4];
            float4 p0, p1;
            p0.x = __expf(s0.x - m0); p0.y = __expf(s0.y - m0);
            p0.z = __expf(s0.z - m0); p0.w = __expf(s0.w - m0);
            p1.x = __expf(s1.x - m1); p1.y = __expf(s1.y - m1);
            p1.z = __expf(s1.z - m1); p1.w = __expf(s1.w - m1);
            rsum0 += p0.x + p0.y + p0.z + p0.w;
            rsum1 += p1.x + p1.y + p1.z + p1.w;
            *(float4*)&Ps[sr]     [sc * 4] = p0;
            *(float4*)&Ps[sr + 16][sc * 4] = p1;
        }
        // stage hs: 64 x 64
        const float4* hg  = (const float4*)(g_h + (size_t)j0 * F);
        float4*       hs4 = (float4*)&hs[0][0];
#pragma unroll
        for (int u = 0; u < 4; u++) hs4[tid + u * 256] = hg[tid + u * 256];
        __syncthreads();

#pragma unroll 4
        for (int jq = 0; jq < 16; jq++) {
            float4 p4 = *(const float4*)&Ps[ty][jq * 4];
#define STEP(q, pv) { \
            u64 pp = dupf(pv); \
            ulonglong2 ha = *(const ulonglong2*)&hs[jq * 4 + q][tx * 8]; \
            ulonglong2 hb = *(const ulonglong2*)&hs[jq * 4 + q][tx * 8 + 4]; \
            acc0 = f2fma(pp, ha.x, acc0); acc1 = f2fma(pp, ha.y, acc1); \
            acc2 = f2fma(pp, hb.x, acc2); acc3 = f2fma(pp, hb.y, acc3); }
            STEP(0, p4.x) STEP(1, p4.y) STEP(2, p4.z) STEP(3, p4.w)
#undef STEP
        }
    }

    // rowsum reduction: 16-lane groups share sr
#pragma unroll
    for (int o = 8; o >= 1; o >>= 1) {
        rsum0 += __shfl_xor_sync(0xffffffffu, rsum0, o);
        rsum1 += __shfl_xor_sync(0xffffffffu, rsum1, o);
    }
    if ((tid & 15) == 0) {
        atomicAdd(&g_rowsum[row0 + sr],      rsum0);
        atomicAdd(&g_rowsum[row0 + sr + 16], rsum1);
    }

    float o_[8];
    unpack2(acc0, o_[0], o_[1]); unpack2(acc1, o_[2], o_[3]);
    unpack2(acc2, o_[4], o_[5]); unpack2(acc3, o_[6], o_[7]);
    float* dst = &g_opart[gy][(size_t)(row0 + ty) * F + tx * 8];
    *(float4*)dst       = make_float4(o_[0], o_[1], o_[2], o_[3]);
    *(float4*)(dst + 4) = make_float4(o_[4], o_[5], o_[6], o_[7]);
}

// ---------------- K4: out = relu((sum of partials) / rowsum) --------------
__global__ __launch_bounds__(256) void k4_final(float* __restrict__ out) {
    int idx = blockIdx.x * blockDim.x + threadIdx.x;   // over N*F/4 float4s
    int i = idx >> 4;
    float inv = 1.0f / g_rowsum[i];
    float4 v0 = ((const float4*)g_opart[0])[idx];
    float4 v1 = ((const float4*)g_opart[1])[idx];
    float4 v2 = ((const float4*)g_opart[2])[idx];
    float4 v3 = ((const float4*)g_opart[3])[idx];
    float4 r;
    r.x = fmaxf((v0.x + v1.x + v2.x + v3.x) * inv, 0.f);
    r.y = fmaxf((v0.y + v1.y + v2.y + v3.y) * inv, 0.f);
    r.z = fmaxf((v0.z + v1.z + v2.z + v3.z) * inv, 0.f);
    r.w = fmaxf((v0.w + v1.w + v2.w + v3.w) * inv, 0.f);
    ((float4*)out)[idx] = r;
}

// ---------------- launch ---------------------------------------------------
extern "C" void kernel_launch(void* const* d_in, const int* in_sizes, int n_in,
                              void* d_out, int out_size) {
    const float* x   = (const float*)d_in[0];
    const int*   adj = (const int*)  d_in[1];
    const float* W   = (const float*)d_in[2];
    const float* a   = (const float*)d_in[3];
    float*       out = (float*)d_out;

    init_rows<<<8, 256>>>();
    k1_gemm_h<<<128, 256>>>(x, W);
    dim3 g2(32, 32);
    k2_scores<<<g2, 256>>>(adj, a);
    dim3 g3(64, 4);
    k3_av<<<g3, 256>>>();
    k4_final<<<128, 256>>>(out);
}

// round 3
// speedup vs baseline: 1.6635x; 1.6635x over previous
#include <cuda_runtime.h>

#define N     2048
#define FIN   512
#define F     64
#define NEG_BIG -9.0e15f

typedef unsigned long long u64;

// ---------------- scratch (static device allocations only) ----------------
__device__ float g_h[N * F];                 // 512 KB
__device__ float g_S[(size_t)N * N];         // 16 MB raw scores
__device__ float g_rowmax[N];
__device__ float g_rowsum[N];
__device__ float g_opart[16][N * F];         // 8 MB: j-split partials of P@h

#define ABS2MASK 0x7FFFFFFF7FFFFFFFULL

__device__ __forceinline__ u64 f2add(u64 a, u64 b) {
    u64 r; asm("add.rn.f32x2 %0, %1, %2;" : "=l"(r) : "l"(a), "l"(b)); return r;
}
__device__ __forceinline__ u64 f2fma(u64 a, u64 b, u64 c) {
    u64 r; asm("fma.rn.f32x2 %0, %1, %2, %3;" : "=l"(r) : "l"(a), "l"(b), "l"(c)); return r;
}
__device__ __forceinline__ u64 dupf(float x) {
    u64 r; unsigned u = __float_as_uint(x);
    asm("mov.b64 %0, {%1,%1};" : "=l"(r) : "r"(u)); return r;
}
__device__ __forceinline__ float unpack_sum(u64 v) {
    float lo, hi;
    asm("mov.b64 {%0,%1}, %2;" : "=f"(lo), "=f"(hi) : "l"(v));
    return lo + hi;
}
__device__ __forceinline__ void unpack2(u64 v, float& lo, float& hi) {
    asm("mov.b64 {%0,%1}, %2;" : "=f"(lo), "=f"(hi) : "l"(v));
}

#define FMA4(a, s, v) { (a).x += (s)*(v).x; (a).y += (s)*(v).y; (a).z += (s)*(v).z; (a).w += (s)*(v).w; }

// ---------------- init ------------------------------------------------------
__global__ void init_rows() {
    int i = blockIdx.x * blockDim.x + threadIdx.x;
    if (i < N) { g_rowmax[i] = 0.0f; g_rowsum[i] = 0.0f; }
}

// ---------------- K1: h = x @ W  (N x FIN) @ (FIN x F) ---------------------
// 4 independent accumulator chains for ILP.
__global__ __launch_bounds__(256) void k1_gemm_h(const float* __restrict__ x,
                                                 const float* __restrict__ W) {
    __shared__ float xs[16][FIN];   // 32 KB
    __shared__ float ws[32][F];     // 8 KB
    int tid = threadIdx.x;
    int r0 = blockIdx.x * 16;

    const float4* xg  = (const float4*)(x + (size_t)r0 * FIN);
    float4*       xs4 = (float4*)&xs[0][0];
#pragma unroll
    for (int u = 0; u < 8; u++) xs4[tid + u * 256] = xg[tid + u * 256];

    int tx = tid & 15;
    int ty = tid >> 4;
    float4 acc[4];
#pragma unroll
    for (int q = 0; q < 4; q++) acc[q] = make_float4(0.f, 0.f, 0.f, 0.f);

    for (int kt = 0; kt < FIN; kt += 32) {
        __syncthreads();
        const float4* wg  = (const float4*)(W + (size_t)kt * F);
        float4*       ws4 = (float4*)&ws[0][0];
        ws4[tid]       = wg[tid];
        ws4[tid + 256] = wg[tid + 256];
        __syncthreads();
#pragma unroll
        for (int k4 = 0; k4 < 8; k4++) {
            float4 xv = *(const float4*)&xs[ty][kt + k4 * 4];
            float4 w0 = ((const float4*)&ws[k4 * 4 + 0][0])[tx];
            float4 w1 = ((const float4*)&ws[k4 * 4 + 1][0])[tx];
            float4 w2 = ((const float4*)&ws[k4 * 4 + 2][0])[tx];
            float4 w3 = ((const float4*)&ws[k4 * 4 + 3][0])[tx];
            FMA4(acc[0], xv.x, w0); FMA4(acc[1], xv.y, w1);
            FMA4(acc[2], xv.z, w2); FMA4(acc[3], xv.w, w3);
        }
    }
    float4 r;
    r.x = (acc[0].x + acc[1].x) + (acc[2].x + acc[3].x);
    r.y = (acc[0].y + acc[1].y) + (acc[2].y + acc[3].y);
    r.z = (acc[0].z + acc[1].z) + (acc[2].z + acc[3].z);
    r.w = (acc[0].w + acc[1].w) + (acc[2].w + acc[3].w);
    *(float4*)&g_h[(size_t)(r0 + ty) * F + tx * 4] = r;
}

// ---------------- K2: scores (unchanged from round 2) ----------------------
__global__ __launch_bounds__(256) void k2_scores(const int* __restrict__ adj,
                                                 const float* __restrict__ a) {
    __shared__ float his[64][F];    // 16 KB  [i][f]
    __shared__ float nhjs[64][F];   // 16 KB  [j][f]  (negated)
    __shared__ float as_[F];

    int tid = threadIdx.x;
    int jb = blockIdx.x, ib = blockIdx.y;

    const float4* hgi = (const float4*)(g_h + (size_t)ib * 64 * F);
    const float4* hgj = (const float4*)(g_h + (size_t)jb * 64 * F);
    float4* hip = (float4*)&his[0][0];
    float4* hjp = (float4*)&nhjs[0][0];
#pragma unroll
    for (int u = 0; u < 4; u++) {
        hip[tid + u * 256] = hgi[tid + u * 256];
        float4 v = hgj[tid + u * 256];
        v.x = -v.x; v.y = -v.y; v.z = -v.z; v.w = -v.w;
        hjp[tid + u * 256] = v;
    }
    if (tid < 16) ((float4*)as_)[tid] = ((const float4*)a)[tid];
    __syncthreads();

    int tx = tid & 15, ty = tid >> 4;
    int i0 = ty * 4, j0 = tx * 4;
    u64 acc[4][4] = {};

#pragma unroll
    for (int fc = 0; fc < 16; fc++) {
        int c2 = (fc + tx) & 15;               // rotated f-chunk vs banks
        ulonglong2 av = *(const ulonglong2*)&as_[c2 * 4];
        ulonglong2 hi[4], nj[4];
#pragma unroll
        for (int k = 0; k < 4; k++) {
            hi[k] = *(const ulonglong2*)&his [i0 + k][c2 * 4];
            nj[k] = *(const ulonglong2*)&nhjs[j0 + k][c2 * 4];
        }
#pragma unroll
        for (int k = 0; k < 4; k++) {
#pragma unroll
            for (int jj = 0; jj < 4; jj++) {
                u64 d0 = f2add(hi[k].x, nj[jj].x) & ABS2MASK;
                acc[k][jj] = f2fma(d0, av.x, acc[k][jj]);
                u64 d1 = f2add(hi[k].y, nj[jj].y) & ABS2MASK;
                acc[k][jj] = f2fma(d1, av.y, acc[k][jj]);
            }
        }
    }

    int gi0 = ib * 64 + i0, gj0 = jb * 64 + j0;
#pragma unroll
    for (int k = 0; k < 4; k++) {
        int4 ad = *(const int4*)&adj[(size_t)(gi0 + k) * N + gj0];
        float4 s;
        s.x = (ad.x > 0) ? fmaxf(unpack_sum(acc[k][0]), 0.f) : NEG_BIG;
        s.y = (ad.y > 0) ? fmaxf(unpack_sum(acc[k][1]), 0.f) : NEG_BIG;
        s.z = (ad.z > 0) ? fmaxf(unpack_sum(acc[k][2]), 0.f) : NEG_BIG;
        s.w = (ad.w > 0) ? fmaxf(unpack_sum(acc[k][3]), 0.f) : NEG_BIG;
        float m = fmaxf(fmaxf(s.x, s.y), fmaxf(s.z, s.w));
#pragma unroll
        for (int o = 8; o >= 1; o >>= 1)
            m = fmaxf(m, __shfl_xor_sync(0xffffffffu, m, o));
        if (tx == 0 && m >= 0.f)
            atomicMax((int*)&g_rowmax[gi0 + k], __float_as_int(m)); // valid: values >= 0
        *(float4*)&g_S[(size_t)(gi0 + k) * N + gj0] = s;
    }
}

// ---------------- K3: fused exp + rowsum + P@h (register-blocked GEMM) -----
// Block tile: 128 i x 64 f, j-chunk 128 (2 subtiles of 64). Grid (16, 16).
// Thread micro-tile: 8i x 4f, packed f32x2 over i-pairs.
// Pst[j][i] transposed with XOR swizzle ((j>>2)&7)*4 -> <=2-way conflicts.
// hs2[j][f] pre-duplicated f32x2 features, split layout for 2-way banks.
#define K3_PST_BYTES (64 * 128 * 4)
#define K3_HS2_BYTES (64 * 64 * 8)
#define K3_SMEM (K3_PST_BYTES + K3_HS2_BYTES + 128 * 4)

__global__ __launch_bounds__(256) void k3_av() {
    extern __shared__ char smraw[];
    float* Pst = (float*)smraw;                          // [64][128] swizzled
    u64*   hs2 = (u64*)(smraw + K3_PST_BYTES);           // [64][64]
    float* ms  = (float*)(smraw + K3_PST_BYTES + K3_HS2_BYTES); // [128]

    int tid = threadIdx.x;
    int ib = blockIdx.x, gy = blockIdx.y;
    int row0 = ib * 128;

    if (tid < 128) ms[tid] = g_rowmax[row0 + tid];

    int tx = tid & 15, ty = tid >> 4;   // micro: f4-col tx, rows i0..i0+7
    int i0 = ty * 8;
    int sr = ty;                        // staging row-in-pass / j-in-pass
    int sj = tx;                        // staging 4-col

    u64 acc[4][4] = {};                 // [f][i-pair]
    float rsum[8] = {0.f,0.f,0.f,0.f,0.f,0.f,0.f,0.f};

    __syncthreads();

    for (int sub = 0; sub < 2; sub++) {
        int j0 = gy * 128 + sub * 64;
        if (sub) __syncthreads();

        // ---- stage Pst (transposed + swizzled) with fused exp + rowsum ----
        int swz_s = (sj & 7) * 4;       // == ((j>>2)&7)*4 for j = 4*sj + q
#pragma unroll
        for (int rp = 0; rp < 8; rp++) {
            int r = rp * 16 + sr;
            float m = ms[r];
            float4 s = *(const float4*)&g_S[(size_t)(row0 + r) * N + j0 + sj * 4];
            float4 p;
            p.x = __expf(s.x - m); p.y = __expf(s.y - m);
            p.z = __expf(s.z - m); p.w = __expf(s.w - m);
            rsum[rp] += (p.x + p.y) + (p.z + p.w);
            int ri = r ^ swz_s;
            Pst[(sj * 4 + 0) * 128 + ri] = p.x;
            Pst[(sj * 4 + 1) * 128 + ri] = p.y;
            Pst[(sj * 4 + 2) * 128 + ri] = p.z;
            Pst[(sj * 4 + 3) * 128 + ri] = p.w;
        }

        // ---- stage hs2: duplicated f32x2 features, split-pair layout ----
#pragma unroll
        for (int hp = 0; hp < 4; hp++) {
            int jq = hp * 16 + sr;
            float4 hv = *(const float4*)&g_h[(size_t)(j0 + jq) * F + sj * 4];
            u64* rowp = &hs2[jq * 64];
            rowp[2 * sj + 0]      = dupf(hv.x);
            rowp[2 * sj + 1]      = dupf(hv.y);
            rowp[32 + 2 * sj + 0] = dupf(hv.z);
            rowp[32 + 2 * sj + 1] = dupf(hv.w);
        }
        __syncthreads();

        // ---- micro loop: 64 j steps, 16 f2fma + 4 LDS.128 each ----
#pragma unroll 4
        for (int jq = 0; jq < 64; jq++) {
            int swz = ((jq >> 2) & 7) * 4;
            const float* prow = &Pst[jq * 128];
            int pa_off = i0 ^ swz;
            ulonglong2 pa = *(const ulonglong2*)&prow[pa_off];
            ulonglong2 pb = *(const ulonglong2*)&prow[pa_off ^ 4];
            const u64* hrow = &hs2[jq * 64];
            ulonglong2 hA = *(const ulonglong2*)&hrow[2 * tx];
            ulonglong2 hB = *(const ulonglong2*)&hrow[32 + 2 * tx];

            acc[0][0] = f2fma(pa.x, hA.x, acc[0][0]);
            acc[0][1] = f2fma(pa.y, hA.x, acc[0][1]);
            acc[0][2] = f2fma(pb.x, hA.x, acc[0][2]);
            acc[0][3] = f2fma(pb.y, hA.x, acc[0][3]);
            acc[1][0] = f2fma(pa.x, hA.y, acc[1][0]);
            acc[1][1] = f2fma(pa.y, hA.y, acc[1][1]);
            acc[1][2] = f2fma(pb.x, hA.y, acc[1][2]);
            acc[1][3] = f2fma(pb.y, hA.y, acc[1][3]);
            acc[2][0] = f2fma(pa.x, hB.x, acc[2][0]);
            acc[2][1] = f2fma(pa.y, hB.x, acc[2][1]);
            acc[2][2] = f2fma(pb.x, hB.x, acc[2][2]);
            acc[2][3] = f2fma(pb.y, hB.x, acc[2][3]);
            acc[3][0] = f2fma(pa.x, hB.y, acc[3][0]);
            acc[3][1] = f2fma(pa.y, hB.y, acc[3][1]);
            acc[3][2] = f2fma(pb.x, hB.y, acc[3][2]);
            acc[3][3] = f2fma(pb.y, hB.y, acc[3][3]);
        }
    }

    // ---- rowsum: reduce over 16 tx lanes sharing each row, then atomic ----
#pragma unroll
    for (int o = 8; o >= 1; o >>= 1) {
#pragma unroll
        for (int rp = 0; rp < 8; rp++)
            rsum[rp] += __shfl_xor_sync(0xffffffffu, rsum[rp], o);
    }
    if (tx == 0) {
#pragma unroll
        for (int rp = 0; rp < 8; rp++)
            atomicAdd(&g_rowsum[row0 + rp * 16 + sr], rsum[rp]);
    }

    // ---- epilogue: unpack acc pairs, write opart ----
#pragma unroll
    for (int ip = 0; ip < 4; ip++) {
        float lo0, hi0, lo1, hi1, lo2, hi2, lo3, hi3;
        unpack2(acc[0][ip], lo0, hi0);
        unpack2(acc[1][ip], lo1, hi1);
        unpack2(acc[2][ip], lo2, hi2);
        unpack2(acc[3][ip], lo3, hi3);
        float* d0 = &g_opart[gy][(size_t)(row0 + i0 + 2 * ip) * F + tx * 4];
        *(float4*)d0       = make_float4(lo0, lo1, lo2, lo3);
        *(float4*)(d0 + F) = make_float4(hi0, hi1, hi2, hi3);
    }
}

// ---------------- K4: out = relu((sum of 16 partials) / rowsum) ------------
__global__ __launch_bounds__(256) void k4_final(float* __restrict__ out) {
    int idx = blockIdx.x * blockDim.x + threadIdx.x;   // over N*F/4 float4s
    int i = idx >> 4;
    float inv = 1.0f / g_rowsum[i];
    float4 s = make_float4(0.f, 0.f, 0.f, 0.f);
#pragma unroll
    for (int p = 0; p < 16; p++) {
        float4 v = ((const float4*)g_opart[p])[idx];
        s.x += v.x; s.y += v.y; s.z += v.z; s.w += v.w;
    }
    float4 r;
    r.x = fmaxf(s.x * inv, 0.f);
    r.y = fmaxf(s.y * inv, 0.f);
    r.z = fmaxf(s.z * inv, 0.f);
    r.w = fmaxf(s.w * inv, 0.f);
    ((float4*)out)[idx] = r;
}

// ---------------- launch ---------------------------------------------------
extern "C" void kernel_launch(void* const* d_in, const int* in_sizes, int n_in,
                              void* d_out, int out_size) {
    const float* x   = (const float*)d_in[0];
    const int*   adj = (const int*)  d_in[1];
    const float* W   = (const float*)d_in[2];
    const float* a   = (const float*)d_in[3];
    float*       out = (float*)d_out;

    cudaFuncSetAttribute(k3_av, cudaFuncAttributeMaxDynamicSharedMemorySize, K3_SMEM);

    init_rows<<<8, 256>>>();
    k1_gemm_h<<<128, 256>>>(x, W);
    dim3 g2(32, 32);
    k2_scores<<<g2, 256>>>(adj, a);
    dim3 g3(16, 16);
    k3_av<<<g3, 256, K3_SMEM>>>();
    k4_final<<<128, 256>>>(out);
}

// round 4
// speedup vs baseline: 1.8782x; 1.1291x over previous
#include <cuda_runtime.h>

#define N     2048
#define FIN   512
#define F     64
#define NEG_BIG -9.0e15f

typedef unsigned long long u64;

// ---------------- scratch (static device allocations only) ----------------
__device__ float g_h[N * F];                 // 512 KB
__device__ float g_S[(size_t)N * N];         // 16 MB raw scores
__device__ float g_rowmax[N];
__device__ float g_rowsum[N];
__device__ float g_opart[16][N * F];         // 8 MB: j-split partials of P@h

#define ABS2MASK 0x7FFFFFFF7FFFFFFFULL

__device__ __forceinline__ u64 f2add(u64 a, u64 b) {
    u64 r; asm("add.rn.f32x2 %0, %1, %2;" : "=l"(r) : "l"(a), "l"(b)); return r;
}
__device__ __forceinline__ u64 f2fma(u64 a, u64 b, u64 c) {
    u64 r; asm("fma.rn.f32x2 %0, %1, %2, %3;" : "=l"(r) : "l"(a), "l"(b), "l"(c)); return r;
}
__device__ __forceinline__ u64 dupf(float x) {
    u64 r; unsigned u = __float_as_uint(x);
    asm("mov.b64 %0, {%1,%1};" : "=l"(r) : "r"(u)); return r;
}
__device__ __forceinline__ float unpack_sum(u64 v) {
    float lo, hi;
    asm("mov.b64 {%0,%1}, %2;" : "=f"(lo), "=f"(hi) : "l"(v));
    return lo + hi;
}
__device__ __forceinline__ void unpack2(u64 v, float& lo, float& hi) {
    asm("mov.b64 {%0,%1}, %2;" : "=f"(lo), "=f"(hi) : "l"(v));
}

#define FMA4(a, s, v) { (a).x += (s)*(v).x; (a).y += (s)*(v).y; (a).z += (s)*(v).z; (a).w += (s)*(v).w; }

// ---------------- init ------------------------------------------------------
__global__ void init_rows() {
    int i = blockIdx.x * blockDim.x + threadIdx.x;
    if (i < N) { g_rowmax[i] = 0.0f; g_rowsum[i] = 0.0f; }
}

// ---------------- K1: h = x @ W  (N x FIN) @ (FIN x F) ---------------------
__global__ __launch_bounds__(256) void k1_gemm_h(const float* __restrict__ x,
                                                 const float* __restrict__ W) {
    __shared__ float xs[16][FIN];   // 32 KB
    __shared__ float ws[32][F];     // 8 KB
    int tid = threadIdx.x;
    int r0 = blockIdx.x * 16;

    const float4* xg  = (const float4*)(x + (size_t)r0 * FIN);
    float4*       xs4 = (float4*)&xs[0][0];
#pragma unroll
    for (int u = 0; u < 8; u++) xs4[tid + u * 256] = xg[tid + u * 256];

    int tx = tid & 15;
    int ty = tid >> 4;
    float4 acc[4];
#pragma unroll
    for (int q = 0; q < 4; q++) acc[q] = make_float4(0.f, 0.f, 0.f, 0.f);

    for (int kt = 0; kt < FIN; kt += 32) {
        __syncthreads();
        const float4* wg  = (const float4*)(W + (size_t)kt * F);
        float4*       ws4 = (float4*)&ws[0][0];
        ws4[tid]       = wg[tid];
        ws4[tid + 256] = wg[tid + 256];
        __syncthreads();
#pragma unroll
        for (int k4 = 0; k4 < 8; k4++) {
            float4 xv = *(const float4*)&xs[ty][kt + k4 * 4];
            float4 w0 = ((const float4*)&ws[k4 * 4 + 0][0])[tx];
            float4 w1 = ((const float4*)&ws[k4 * 4 + 1][0])[tx];
            float4 w2 = ((const float4*)&ws[k4 * 4 + 2][0])[tx];
            float4 w3 = ((const float4*)&ws[k4 * 4 + 3][0])[tx];
            FMA4(acc[0], xv.x, w0); FMA4(acc[1], xv.y, w1);
            FMA4(acc[2], xv.z, w2); FMA4(acc[3], xv.w, w3);
        }
    }
    float4 r;
    r.x = (acc[0].x + acc[1].x) + (acc[2].x + acc[3].x);
    r.y = (acc[0].y + acc[1].y) + (acc[2].y + acc[3].y);
    r.z = (acc[0].z + acc[1].z) + (acc[2].z + acc[3].z);
    r.w = (acc[0].w + acc[1].w) + (acc[2].w + acc[3].w);
    *(float4*)&g_h[(size_t)(r0 + ty) * F + tx * 4] = r;
}

// ---------------- K2: symmetric scores, upper-triangle tiles ----------------
// e[i,j] = e[j,i]; compute 64x64 tile once (ib<=jb), write both orientations
// with their own adj masks. Rotated-store smem layout:
//   element (row, f-chunk c) stored at physical chunk (c + row/4) & 15.
// Reads: hi -> broadcast (lanes share ty), nj -> 16 chunks 2-way. a: bcast.
__global__ __launch_bounds__(256) void k2_scores(const int* __restrict__ adj,
                                                 const float* __restrict__ a) {
    __shared__ float sm[2 * 4096 + 64];
    float* his  = sm;          // [64][64] rotated
    float* nhjs = sm + 4096;   // [64][64] rotated, negated
    float* as_  = sm + 8192;   // [64]

    int tid = threadIdx.x;
    int jb = blockIdx.x, ib = blockIdx.y;
    if (jb < ib) return;                  // whole block exits: safe

    const float4* hgi = (const float4*)(g_h + (size_t)ib * 64 * F);
    const float4* hgj = (const float4*)(g_h + (size_t)jb * 64 * F);
#pragma unroll
    for (int u = 0; u < 4; u++) {
        int v = tid + u * 256;
        int r = v >> 4, c = v & 15;
        int cp = (c + (r >> 2)) & 15;
        *(float4*)&his[r * 64 + cp * 4] = hgi[v];
        float4 nv = hgj[v];
        nv.x = -nv.x; nv.y = -nv.y; nv.z = -nv.z; nv.w = -nv.w;
        *(float4*)&nhjs[r * 64 + cp * 4] = nv;
    }
    if (tid < 16) ((float4*)as_)[tid] = ((const float4*)a)[tid];
    __syncthreads();

    int tx = tid & 15, ty = tid >> 4;
    int i0 = ty * 4, j0 = tx * 4;
    u64 acc[4][4] = {};

#pragma unroll
    for (int fc = 0; fc < 16; fc++) {
        ulonglong2 av = *(const ulonglong2*)&as_[fc * 4];
        int ci = ((fc + ty) & 15) * 4;
        int cj = ((fc + tx) & 15) * 4;
        ulonglong2 hr[4], nj[4];
#pragma unroll
        for (int k = 0; k < 4; k++) {
            hr[k] = *(const ulonglong2*)&his [(i0 + k) * 64 + ci];
            nj[k] = *(const ulonglong2*)&nhjs[(j0 + k) * 64 + cj];
        }
#pragma unroll
        for (int k = 0; k < 4; k++) {
#pragma unroll
            for (int jj = 0; jj < 4; jj++) {
                u64 d0 = f2add(hr[k].x, nj[jj].x) & ABS2MASK;
                acc[k][jj] = f2fma(d0, av.x, acc[k][jj]);
                u64 d1 = f2add(hr[k].y, nj[jj].y) & ABS2MASK;
                acc[k][jj] = f2fma(d1, av.y, acc[k][jj]);
            }
        }
    }

    float sc[4][4];
#pragma unroll
    for (int k = 0; k < 4; k++)
#pragma unroll
        for (int jj = 0; jj < 4; jj++)
            sc[k][jj] = fmaxf(unpack_sum(acc[k][jj]), 0.f);

    // ---- normal orientation: rows gi, cols gj ----
    int gi0 = ib * 64 + i0, gj0 = jb * 64 + j0;
#pragma unroll
    for (int k = 0; k < 4; k++) {
        int4 ad = *(const int4*)&adj[(size_t)(gi0 + k) * N + gj0];
        float4 s;
        s.x = (ad.x > 0) ? sc[k][0] : NEG_BIG;
        s.y = (ad.y > 0) ? sc[k][1] : NEG_BIG;
        s.z = (ad.z > 0) ? sc[k][2] : NEG_BIG;
        s.w = (ad.w > 0) ? sc[k][3] : NEG_BIG;
        float m = fmaxf(fmaxf(s.x, s.y), fmaxf(s.z, s.w));
#pragma unroll
        for (int o = 8; o >= 1; o >>= 1)
            m = fmaxf(m, __shfl_xor_sync(0xffffffffu, m, o));
        if (tx == 0 && m >= 0.f)
            atomicMax((int*)&g_rowmax[gi0 + k], __float_as_int(m));
        *(float4*)&g_S[(size_t)(gi0 + k) * N + gj0] = s;
    }

    // ---- transposed orientation: rows gj, cols gi (off-diagonal only) ----
    if (ib != jb) {
        __syncthreads();                  // his/nhjs reads done; reuse as ts
        float* ts = sm;                   // [64][68]
#pragma unroll
        for (int k = 0; k < 4; k++)
#pragma unroll
            for (int jj = 0; jj < 4; jj++)
                ts[(j0 + jj) * 68 + i0 + k] = sc[k][jj];
        __syncthreads();
#pragma unroll
        for (int rp = 0; rp < 4; rp++) {
            int jr = rp * 16 + ty;
            float4 v = *(const float4*)&ts[jr * 68 + tx * 4];
            int4 ad = *(const int4*)&adj[(size_t)(jb * 64 + jr) * N + ib * 64 + tx * 4];
            float4 s;
            s.x = (ad.x > 0) ? v.x : NEG_BIG;
            s.y = (ad.y > 0) ? v.y : NEG_BIG;
            s.z = (ad.z > 0) ? v.z : NEG_BIG;
            s.w = (ad.w > 0) ? v.w : NEG_BIG;
            float m = fmaxf(fmaxf(s.x, s.y), fmaxf(s.z, s.w));
#pragma unroll
            for (int o = 8; o >= 1; o >>= 1)
                m = fmaxf(m, __shfl_xor_sync(0xffffffffu, m, o));
            if (tx == 0 && m >= 0.f)
                atomicMax((int*)&g_rowmax[jb * 64 + jr], __float_as_int(m));
            *(float4*)&g_S[(size_t)(jb * 64 + jr) * N + ib * 64 + tx * 4] = s;
        }
    }
}

// ---------------- K3: fused exp + rowsum + P@h (register-blocked GEMM) -----
// Block tile: 128 i x 64 f, j-chunk 128 (2 subtiles of 64). Grid (16, 16).
// Software pipelined: next subtile's S prefetched into registers before the
// micro loop so L2 latency hides under ~2000 cycles of f2fma.
#define K3_PST_BYTES (64 * 128 * 4)
#define K3_HS2_BYTES (64 * 64 * 8)
#define K3_SMEM (K3_PST_BYTES + K3_HS2_BYTES + 128 * 4)

__global__ __launch_bounds__(256) void k3_av() {
    extern __shared__ char smraw[];
    float* Pst = (float*)smraw;                          // [64][128] swizzled
    u64*   hs2 = (u64*)(smraw + K3_PST_BYTES);           // [64][64]
    float* ms  = (float*)(smraw + K3_PST_BYTES + K3_HS2_BYTES); // [128]

    int tid = threadIdx.x;
    int ib = blockIdx.x, gy = blockIdx.y;
    int row0 = ib * 128;

    if (tid < 128) ms[tid] = g_rowmax[row0 + tid];

    int tx = tid & 15, ty = tid >> 4;   // micro: f4-col tx, rows i0..i0+7
    int i0 = ty * 8;
    int sr = ty;                        // staging row-in-pass
    int sj = tx;                        // staging 4-col

    u64 acc[4][4] = {};                 // [f][i-pair]
    float rsum[8] = {0.f,0.f,0.f,0.f,0.f,0.f,0.f,0.f};
    int swz_s = (sj & 7) * 4;

    // prologue: prefetch subtile 0 S
    float4 sreg[8];
    {
        int j0 = gy * 128;
#pragma unroll
        for (int rp = 0; rp < 8; rp++)
            sreg[rp] = *(const float4*)&g_S[(size_t)(row0 + rp * 16 + sr) * N + j0 + sj * 4];
    }
    __syncthreads();

    for (int sub = 0; sub < 2; sub++) {
        int j0 = gy * 128 + sub * 64;
        if (sub) __syncthreads();       // micro loop done reading smem

        // ---- stage Pst (transposed + swizzled) with fused exp + rowsum ----
#pragma unroll
        for (int rp = 0; rp < 8; rp++) {
            int r = rp * 16 + sr;
            float m = ms[r];
            float4 s = sreg[rp];
            float4 p;
            p.x = __expf(s.x - m); p.y = __expf(s.y - m);
            p.z = __expf(s.z - m); p.w = __expf(s.w - m);
            rsum[rp] += (p.x + p.y) + (p.z + p.w);
            int ri = r ^ swz_s;
            Pst[(sj * 4 + 0) * 128 + ri] = p.x;
            Pst[(sj * 4 + 1) * 128 + ri] = p.y;
            Pst[(sj * 4 + 2) * 128 + ri] = p.z;
            Pst[(sj * 4 + 3) * 128 + ri] = p.w;
        }

        // ---- stage hs2: duplicated f32x2 features ----
#pragma unroll
        for (int hp = 0; hp < 4; hp++) {
            int jq = hp * 16 + sr;
            float4 hv = *(const float4*)&g_h[(size_t)(j0 + jq) * F + sj * 4];
            u64* rowp = &hs2[jq * 64];
            rowp[2 * sj + 0]      = dupf(hv.x);
            rowp[2 * sj + 1]      = dupf(hv.y);
            rowp[32 + 2 * sj + 0] = dupf(hv.z);
            rowp[32 + 2 * sj + 1] = dupf(hv.w);
        }
        __syncthreads();

        // ---- prefetch next subtile's S (hidden under micro loop) ----
        if (sub == 0) {
            int j1 = gy * 128 + 64;
#pragma unroll
            for (int rp = 0; rp < 8; rp++)
                sreg[rp] = *(const float4*)&g_S[(size_t)(row0 + rp * 16 + sr) * N + j1 + sj * 4];
        }

        // ---- micro loop: 64 j steps, 16 f2fma + 4 LDS.128 each ----
#pragma unroll 4
        for (int jq = 0; jq < 64; jq++) {
            int swz = ((jq >> 2) & 7) * 4;
            const float* prow = &Pst[jq * 128];
            int pa_off = i0 ^ swz;
            ulonglong2 pa = *(const ulonglong2*)&prow[pa_off];
            ulonglong2 pb = *(const ulonglong2*)&prow[pa_off ^ 4];
            const u64* hrow = &hs2[jq * 64];
            ulonglong2 hA = *(const ulonglong2*)&hrow[2 * tx];
            ulonglong2 hB = *(const ulonglong2*)&hrow[32 + 2 * tx];

            acc[0][0] = f2fma(pa.x, hA.x, acc[0][0]);
            acc[0][1] = f2fma(pa.y, hA.x, acc[0][1]);
            acc[0][2] = f2fma(pb.x, hA.x, acc[0][2]);
            acc[0][3] = f2fma(pb.y, hA.x, acc[0][3]);
            acc[1][0] = f2fma(pa.x, hA.y, acc[1][0]);
            acc[1][1] = f2fma(pa.y, hA.y, acc[1][1]);
            acc[1][2] = f2fma(pb.x, hA.y, acc[1][2]);
            acc[1][3] = f2fma(pb.y, hA.y, acc[1][3]);
            acc[2][0] = f2fma(pa.x, hB.x, acc[2][0]);
            acc[2][1] = f2fma(pa.y, hB.x, acc[2][1]);
            acc[2][2] = f2fma(pb.x, hB.x, acc[2][2]);
            acc[2][3] = f2fma(pb.y, hB.x, acc[2][3]);
            acc[3][0] = f2fma(pa.x, hB.y, acc[3][0]);
            acc[3][1] = f2fma(pa.y, hB.y, acc[3][1]);
            acc[3][2] = f2fma(pb.x, hB.y, acc[3][2]);
            acc[3][3] = f2fma(pb.y, hB.y, acc[3][3]);
        }
    }

    // ---- rowsum: reduce over 16 tx lanes sharing each row, then atomic ----
#pragma unroll
    for (int o = 8; o >= 1; o >>= 1) {
#pragma unroll
        for (int rp = 0; rp < 8; rp++)
            rsum[rp] += __shfl_xor_sync(0xffffffffu, rsum[rp], o);
    }
    if (tx == 0) {
#pragma unroll
        for (int rp = 0; rp < 8; rp++)
            atomicAdd(&g_rowsum[row0 + rp * 16 + sr], rsum[rp]);
    }

    // ---- epilogue: unpack acc pairs, write opart ----
#pragma unroll
    for (int ip = 0; ip < 4; ip++) {
        float lo0, hi0, lo1, hi1, lo2, hi2, lo3, hi3;
        unpack2(acc[0][ip], lo0, hi0);
        unpack2(acc[1][ip], lo1, hi1);
        unpack2(acc[2][ip], lo2, hi2);
        unpack2(acc[3][ip], lo3, hi3);
        float* d0 = &g_opart[gy][(size_t)(row0 + i0 + 2 * ip) * F + tx * 4];
        *(float4*)d0       = make_float4(lo0, lo1, lo2, lo3);
        *(float4*)(d0 + F) = make_float4(hi0, hi1, hi2, hi3);
    }
}

// ---------------- K4: out = relu((sum of 16 partials) / rowsum) ------------
__global__ __launch_bounds__(256) void k4_final(float* __restrict__ out) {
    int idx = blockIdx.x * blockDim.x + threadIdx.x;   // over N*F/4 float4s
    int i = idx >> 4;
    float inv = 1.0f / g_rowsum[i];
    float4 s = make_float4(0.f, 0.f, 0.f, 0.f);
#pragma unroll
    for (int p = 0; p < 16; p++) {
        float4 v = ((const float4*)g_opart[p])[idx];
        s.x += v.x; s.y += v.y; s.z += v.z; s.w += v.w;
    }
    float4 r;
    r.x = fmaxf(s.x * inv, 0.f);
    r.y = fmaxf(s.y * inv, 0.f);
    r.z = fmaxf(s.z * inv, 0.f);
    r.w = fmaxf(s.w * inv, 0.f);
    ((float4*)out)[idx] = r;
}

// ---------------- launch ---------------------------------------------------
extern "C" void kernel_launch(void* const* d_in, const int* in_sizes, int n_in,
                              void* d_out, int out_size) {
    const float* x   = (const float*)d_in[0];
    const int*   adj = (const int*)  d_in[1];
    const float* W   = (const float*)d_in[2];
    const float* a   = (const float*)d_in[3];
    float*       out = (float*)d_out;

    cudaFuncSetAttribute(k3_av, cudaFuncAttributeMaxDynamicSharedMemorySize, K3_SMEM);

    init_rows<<<8, 256>>>();
    k1_gemm_h<<<128, 256>>>(x, W);
    dim3 g2(32, 32);
    k2_scores<<<g2, 256>>>(adj, a);
    dim3 g3(16, 16);
    k3_av<<<g3, 256, K3_SMEM>>>();
    k4_final<<<128, 256>>>(out);
}